// round 5
// baseline (speedup 1.0000x reference)
#include <cuda_runtime.h>
#include <cuda_bf16.h>
#include <cuda_fp16.h>
#include <math.h>
#include <stdint.h>

// Problem constants
#define BATCH 16
#define NPATCH 4096
#define KTOK 32
#define DIM 512
#define DHEAD 256
#define SCALE_V 0.0625f   // 256^-0.5

#define SPLITS 16         // n-splits; grid = 16 x 16 = 256 blocks (2/SM resident)
#define NBLK (SPLITS*BATCH)

// Scratch (no allocation allowed -> device globals)
__device__ float g_Q   [BATCH*KTOK*DHEAD];
__device__ float g_Qk  [BATCH*KTOK*DIM];
__device__ float g_Gp  [SPLITS*BATCH*KTOK*DIM];   // 16 MB partials
__device__ float g_G   [BATCH*KTOK*DIM];
__device__ float g_Wc  [DIM*DIM];                  // Wcomb = Wo @ Wv
__device__ float g_rows[BATCH*KTOK*SPLITS];
__device__ unsigned g_barcnt;
__device__ unsigned g_bargen;

// ---------------------------------------------------------------------------

#define LDSM4(R0,R1,R2,R3,ADDR) \
    asm volatile("ldmatrix.sync.aligned.m8n8.x4.shared.b16 {%0,%1,%2,%3}, [%4];" \
        : "=r"(R0),"=r"(R1),"=r"(R2),"=r"(R3) : "r"(ADDR))

#define LDSM4T(R0,R1,R2,R3,ADDR) \
    asm volatile("ldmatrix.sync.aligned.m8n8.x4.trans.shared.b16 {%0,%1,%2,%3}, [%4];" \
        : "=r"(R0),"=r"(R1),"=r"(R2),"=r"(R3) : "r"(ADDR))

#define MMA_BF16(C,A,B0,B1) \
    asm volatile("mma.sync.aligned.m16n8k16.row.col.f32.bf16.bf16.f32 " \
        "{%0,%1,%2,%3},{%4,%5,%6,%7},{%8,%9},{%0,%1,%2,%3};" \
        : "+f"((C)[0]),"+f"((C)[1]),"+f"((C)[2]),"+f"((C)[3]) \
        : "r"((A)[0]),"r"((A)[1]),"r"((A)[2]),"r"((A)[3]),"r"(B0),"r"(B1))

#define MMA_F16(C,A,B0,B1) \
    asm volatile("mma.sync.aligned.m16n8k16.row.col.f32.f16.f16.f32 " \
        "{%0,%1,%2,%3},{%4,%5,%6,%7},{%8,%9},{%0,%1,%2,%3};" \
        : "+f"((C)[0]),"+f"((C)[1]),"+f"((C)[2]),"+f"((C)[3]) \
        : "r"((A)[0]),"r"((A)[1]),"r"((A)[2]),"r"((A)[3]),"r"(B0),"r"(B1))

__device__ __forceinline__ uint32_t cvta_s(const void* p) {
    return (uint32_t)__cvta_generic_to_shared(p);
}

__device__ __forceinline__ uint2 cvt_h4(float4 v) {
    __half2 h0 = __floats2half2_rn(v.x, v.y);
    __half2 h1 = __floats2half2_rn(v.z, v.w);
    uint2 r; r.x = *(uint32_t*)&h0; r.y = *(uint32_t*)&h1; return r;
}

__device__ __forceinline__ void cvt_split4(float4 v, uint2 &hi, uint2 &lo) {
    __nv_bfloat162 h0 = __floats2bfloat162_rn(v.x, v.y);
    __nv_bfloat162 h1 = __floats2bfloat162_rn(v.z, v.w);
    float rx = v.x - __bfloat162float(h0.x);
    float ry = v.y - __bfloat162float(h0.y);
    float rz = v.z - __bfloat162float(h1.x);
    float rw = v.w - __bfloat162float(h1.y);
    __nv_bfloat162 l0 = __floats2bfloat162_rn(rx, ry);
    __nv_bfloat162 l1 = __floats2bfloat162_rn(rz, rw);
    hi.x = *(uint32_t*)&h0; hi.y = *(uint32_t*)&h1;
    lo.x = *(uint32_t*)&l0; lo.y = *(uint32_t*)&l1;
}

// Grid-wide barrier: valid because all NBLK blocks are co-resident
// (256 blocks, 2 blocks/SM * 148 SMs = 296 slots).
__device__ __forceinline__ void grid_barrier() {
    __syncthreads();
    if (threadIdx.x == 0) {
        __threadfence();
        unsigned gen = atomicAdd(&g_bargen, 0u);
        if (atomicAdd(&g_barcnt, 1u) == NBLK - 1u) {
            atomicExch(&g_barcnt, 0u);
            __threadfence();
            atomicAdd(&g_bargen, 1u);
        } else {
            while (atomicAdd(&g_bargen, 0u) == gen) { __nanosleep(128); }
        }
    }
    __syncthreads();
}

// ===========================================================================
// FUSED attention kernel, v2. Block = (n-split sp, batch b), 256 thr, occ 2.
//   4 chunks of 64 E-rows:
//     stage E[64,512] fp32->fp16 smem (one shot)
//     phase1: S[32,64] = Qk_res @ Echunk^T  -> exp -> A(unnorm) + expS smem
//     phase2: accG[32,512] += expS @ Echunk
//   write Gp partial + row-sum partial
//   GRID BARRIER
//   post: distributed G reduction; A slice rescale by 1/rowsum.
// ===========================================================================
#define QK_OFF   0
#define QK_PITCH 1040
#define E_OFF    33280         // 32*1040
#define E_PITCH  1040
#define ES_OFF   99840         // E_OFF + 64*1040
#define ES_PITCH 144           // 64 fp16 + 8 pad
#define RED_OFF  104448        // ES_OFF + 32*144
#define SMEM_FUSED 104960

__global__ __launch_bounds__(256, 2)
void fused_attn2(const float* __restrict__ Qk, const float* __restrict__ E,
                 const float* __restrict__ P, float* __restrict__ outA,
                 float* __restrict__ Gp, float* __restrict__ G,
                 float* __restrict__ rows)
{
    extern __shared__ __align__(16) unsigned char sm[];
    const int sp = blockIdx.x;         // 0..15
    const int b  = blockIdx.y;         // 0..15
    const int tid  = threadIdx.x;
    const int lane = tid & 31;
    const int warp = tid >> 5;
    const int mw = warp >> 2;          // 0..1
    const int nw = warp & 3;           // 0..3

    const float* Eb  = E  + (long)b*NPATCH*DIM;
    const float* Qkb = Qk + (long)b*KTOK*DIM;
    const float* Pb  = P  + (long)b*NPATCH;
    float*       Ab  = outA + (long)b*KTOK*NPATCH;

    // resident Qk [32,512] fp16
    #pragma unroll
    for (int p = 0; p < 16; ++p) {
        int lin = tid + p*256;
        int r = lin >> 7, c4 = lin & 127;
        float4 v = *(const float4*)(Qkb + r*DIM + 4*c4);
        *(uint2*)(sm + QK_OFF + r*QK_PITCH + 8*c4) = cvt_h4(v);
    }

    float accG[16][4];
    #pragma unroll
    for (int t2 = 0; t2 < 16; ++t2)
        #pragma unroll
        for (int r = 0; r < 4; ++r) accG[t2][r] = 0.f;
    float rsum0 = 0.f, rsum8 = 0.f;

    const uint32_t smb = cvta_s(sm);
    const uint32_t aQkBase = smb + QK_OFF + (mw*16 + (lane & 15))*QK_PITCH + (lane >> 4)*16;
    const uint32_t b1Base  = smb + E_OFF
        + (nw*16 + (lane & 7) + ((lane >> 4) & 1)*8)*E_PITCH + ((lane >> 3) & 1)*16;
    const uint32_t aEsBase = smb + ES_OFF + (mw*16 + (lane & 15))*ES_PITCH + (lane >> 4)*16;
    const uint32_t b2Base  = smb + E_OFF + (lane & 15)*E_PITCH + nw*256 + ((lane >> 4) & 1)*16;

    const int nbase = sp * (NPATCH/SPLITS);   // 256-row slice

    for (int c = 0; c < 4; ++c) {
        const int n0 = nbase + c*64;
        __syncthreads();   // protect E & expS reuse
        // ---- stage E[64,512] ----
        #pragma unroll 8
        for (int p = 0; p < 32; ++p) {
            int lin = tid + p*256;
            int r = lin >> 7, c4 = lin & 127;
            float4 v = *(const float4*)(Eb + (long)(n0 + r)*DIM + 4*c4);
            *(uint2*)(sm + E_OFF + r*E_PITCH + 8*c4) = cvt_h4(v);
        }
        __syncthreads();

        // ---- phase 1: S = Qk @ Echunk^T ----
        float sacc[2][4];
        #pragma unroll
        for (int j = 0; j < 2; ++j)
            #pragma unroll
            for (int r = 0; r < 4; ++r) sacc[j][r] = 0.f;
        #pragma unroll
        for (int ks = 0; ks < 32; ++ks) {
            uint32_t a[4], r0, r1, r2, r3;
            LDSM4(a[0],a[1],a[2],a[3], aQkBase + ks*32);
            LDSM4(r0,r1,r2,r3, b1Base + ks*32);
            MMA_F16(sacc[0], a, r0, r1);
            MMA_F16(sacc[1], a, r2, r3);
        }

        // ---- epilogue: exp + A(unnorm) out + expS smem + row sums ----
        {
            const int mrow = mw*16 + (lane >> 2);
            #pragma unroll
            for (int j = 0; j < 2; ++j) {
                int nl = nw*16 + j*8 + 2*(lane & 3);
                int gn = n0 + nl;
                float lp0 = __logf(fminf(fmaxf(Pb[gn],   0.1f), 0.9f));
                float lp1 = __logf(fminf(fmaxf(Pb[gn+1], 0.1f), 0.9f));
                float v0 = __expf(sacc[j][0]*SCALE_V + lp0);
                float v1 = __expf(sacc[j][1]*SCALE_V + lp1);
                float v2 = __expf(sacc[j][2]*SCALE_V + lp0);
                float v3 = __expf(sacc[j][3]*SCALE_V + lp1);
                rsum0 += v0 + v1; rsum8 += v2 + v3;
                *(float2*)(Ab + (long)mrow*NPATCH + gn)     = make_float2(v0, v1);
                *(float2*)(Ab + (long)(mrow+8)*NPATCH + gn) = make_float2(v2, v3);
                __half2 h01 = __floats2half2_rn(v0, v1);
                __half2 h23 = __floats2half2_rn(v2, v3);
                *(uint32_t*)(sm + ES_OFF + mrow*ES_PITCH + nl*2)     = *(uint32_t*)&h01;
                *(uint32_t*)(sm + ES_OFF + (mrow+8)*ES_PITCH + nl*2) = *(uint32_t*)&h23;
            }
        }
        __syncthreads();

        // ---- phase 2: accG += expS @ Echunk ----
        #pragma unroll
        for (int ks = 0; ks < 4; ++ks) {
            uint32_t a[4];
            LDSM4(a[0],a[1],a[2],a[3], aEsBase + ks*32);
            #pragma unroll
            for (int jt = 0; jt < 8; ++jt) {
                uint32_t r0, r1, r2, r3;
                LDSM4T(r0,r1,r2,r3, b2Base + ks*16*E_PITCH + jt*32);
                MMA_F16(accG[2*jt],   a, r0, r1);
                MMA_F16(accG[2*jt+1], a, r2, r3);
            }
        }
    }

    // ---- write G partial ----
    {
        float* Gpb = Gp + ((long)(b*SPLITS + sp)*KTOK)*DIM;
        const int mrow = mw*16 + (lane >> 2);
        #pragma unroll
        for (int t2 = 0; t2 < 16; ++t2) {
            int d = nw*128 + t2*8 + 2*(lane & 3);
            *(float2*)(Gpb + (long)mrow*DIM + d)     = make_float2(accG[t2][0], accG[t2][1]);
            *(float2*)(Gpb + (long)(mrow+8)*DIM + d) = make_float2(accG[t2][2], accG[t2][3]);
        }
    }

    // ---- row-sum partial ----
    rsum0 += __shfl_xor_sync(0xffffffffu, rsum0, 1);
    rsum0 += __shfl_xor_sync(0xffffffffu, rsum0, 2);
    rsum8 += __shfl_xor_sync(0xffffffffu, rsum8, 1);
    rsum8 += __shfl_xor_sync(0xffffffffu, rsum8, 2);
    {
        float (*srow)[4] = (float(*)[4])(sm + RED_OFF);
        if ((lane & 3) == 0) {
            srow[mw*16 + (lane >> 2)][nw]     = rsum0;
            srow[mw*16 + 8 + (lane >> 2)][nw] = rsum8;
        }
        __syncthreads();
        if (tid < 32) {
            float s = srow[tid][0] + srow[tid][1] + srow[tid][2] + srow[tid][3];
            rows[(b*KTOK + tid)*SPLITS + sp] = s;
        }
    }

    // ================= GRID BARRIER =================
    grid_barrier();

    // ---- post 1: distributed G reduction (each block sums 1024 elems) ----
    {
        const int blkid = b*SPLITS + sp;
        int base = blkid*1024 + tid*4;
        int bb   = base >> 14;            // 32*512 = 16384 per batch
        int rem  = base & 16383;
        const float* Pp = Gp + ((long)bb*SPLITS)*16384 + rem;
        float4 s = make_float4(0.f, 0.f, 0.f, 0.f);
        #pragma unroll
        for (int s2 = 0; s2 < SPLITS; ++s2) {
            float4 v = *(const float4*)(Pp + (long)s2*16384);
            s.x += v.x; s.y += v.y; s.z += v.z; s.w += v.w;
        }
        *(float4*)(G + base) = s;
    }

    // ---- post 2: rescale own A slice by 1/rowsum ----
    {
        float* redf = (float*)(sm + RED_OFF);
        if (tid < 32) {
            float s = 0.f;
            #pragma unroll
            for (int c2 = 0; c2 < SPLITS; ++c2)
                s += rows[(b*KTOK + tid)*SPLITS + c2];
            redf[tid] = 1.f / s;
        }
        __syncthreads();
        float* Abase = Ab + nbase;
        #pragma unroll
        for (int p = 0; p < 8; ++p) {
            int lin = tid + p*256;
            int r = lin >> 6, c4 = lin & 63;     // 64 float4 per 256-col row
            float s = redf[r];
            float4 v = *(float4*)(Abase + (long)r*NPATCH + 4*c4);
            v.x *= s; v.y *= s; v.z *= s; v.w *= s;
            *(float4*)(Abase + (long)r*NPATCH + 4*c4) = v;
        }
    }
}

// ===========================================================================
// fp16 single-MMA GEMM for the small projections (Q, Qk).
// BM=32, BN=128, BK=32, 256 threads. C = A[M,Kin] @ op(B).
// ===========================================================================
#define PITCH_A   80
#define PITCH_B   80
#define PITCH_BT  272
#define HS_A 0
#define HS_B 2560
#define HS_BYTES (2560 + 10240)

template<bool TRANS_B>
__global__ __launch_bounds__(256)
void gemm_h(const float* __restrict__ A, const float* __restrict__ B,
            float* __restrict__ C, int N, int Kin)
{
    __shared__ __align__(16) unsigned char sm[HS_BYTES];

    const int m0 = blockIdx.y * 32;
    const int n0 = blockIdx.x * 128;
    const int tid  = threadIdx.x;
    const int lane = tid & 31;
    const int warp = tid >> 5;
    const int mw = warp >> 2;
    const int nw = warp & 3;

    float acc[4][4];
    #pragma unroll
    for (int j = 0; j < 4; j++)
        #pragma unroll
        for (int r = 0; r < 4; r++) acc[j][r] = 0.f;

    const uint32_t aAddr = cvta_s(sm + HS_A)
        + (mw*16 + (lane & 15))*PITCH_A + (lane >> 4)*16;
    uint32_t bAddr[2];
    if (!TRANS_B) {
        #pragma unroll
        for (int jj = 0; jj < 2; jj++) {
            uint32_t nrow = nw*32 + jj*16 + (lane & 7) + ((lane >> 4) & 1)*8;
            bAddr[jj] = cvta_s(sm + HS_B) + nrow*PITCH_B + ((lane >> 3) & 1)*16;
        }
    } else {
        #pragma unroll
        for (int jj = 0; jj < 2; jj++) {
            uint32_t nB = (nw*32 + jj*16)*2 + ((lane >> 4) & 1)*16;
            bAddr[jj] = cvta_s(sm + HS_B) + (lane & 15)*PITCH_BT + nB;
        }
    }

    const int am  = tid >> 3, ak4 = tid & 7;
    const float* aG = A + (long)(m0 + am)*Kin + 4*ak4;

    float4 pa, pb[4];
    pa = *(const float4*)(aG);
    if (!TRANS_B) {
        #pragma unroll
        for (int p = 0; p < 4; ++p) {
            int lin = tid + p*256;
            pb[p] = *(const float4*)(B + (long)(n0 + (lin >> 3))*Kin + 4*(lin & 7));
        }
    } else {
        #pragma unroll
        for (int p = 0; p < 4; ++p) {
            int lin = tid + p*256;
            pb[p] = *(const float4*)(B + (long)(lin >> 5)*N + n0 + 4*(lin & 31));
        }
    }

    for (int k0 = 0; k0 < Kin; k0 += 32) {
        *(uint2*)(sm + HS_A + am*PITCH_A + 8*ak4) = cvt_h4(pa);
        if (!TRANS_B) {
            #pragma unroll
            for (int p = 0; p < 4; ++p) {
                int lin = tid + p*256;
                *(uint2*)(sm + HS_B + (lin >> 3)*PITCH_B + 8*(lin & 7)) = cvt_h4(pb[p]);
            }
        } else {
            #pragma unroll
            for (int p = 0; p < 4; ++p) {
                int lin = tid + p*256;
                *(uint2*)(sm + HS_B + (lin >> 5)*PITCH_BT + 8*(lin & 31)) = cvt_h4(pb[p]);
            }
        }
        __syncthreads();

        int kn = k0 + 32;
        if (kn < Kin) {
            pa = *(const float4*)(aG + kn);
            if (!TRANS_B) {
                #pragma unroll
                for (int p = 0; p < 4; ++p) {
                    int lin = tid + p*256;
                    pb[p] = *(const float4*)(B + (long)(n0 + (lin >> 3))*Kin + kn + 4*(lin & 7));
                }
            } else {
                #pragma unroll
                for (int p = 0; p < 4; ++p) {
                    int lin = tid + p*256;
                    pb[p] = *(const float4*)(B + (long)(kn + (lin >> 5))*N + n0 + 4*(lin & 31));
                }
            }
        }

        #pragma unroll
        for (int kt = 0; kt < 2; ++kt) {
            uint32_t a[4];
            LDSM4(a[0],a[1],a[2],a[3], aAddr + kt*32);
            uint32_t bf[4][2];
            #pragma unroll
            for (int jj = 0; jj < 2; ++jj) {
                uint32_t r0,r1,r2,r3;
                if (!TRANS_B) {
                    LDSM4(r0,r1,r2,r3, bAddr[jj] + kt*32);
                } else {
                    LDSM4T(r0,r1,r2,r3, bAddr[jj] + kt*16*PITCH_BT);
                }
                bf[2*jj][0]=r0; bf[2*jj][1]=r1; bf[2*jj+1][0]=r2; bf[2*jj+1][1]=r3;
            }
            #pragma unroll
            for (int j = 0; j < 4; ++j)
                MMA_F16(acc[j], a, bf[j][0], bf[j][1]);
        }
        __syncthreads();
    }

    const int mrow = m0 + mw*16 + (lane >> 2);
    #pragma unroll
    for (int j = 0; j < 4; ++j) {
        int n = n0 + nw*32 + j*8 + 2*(lane & 3);
        C[(long)mrow*N + n]       = acc[j][0];
        C[(long)mrow*N + n + 1]   = acc[j][1];
        C[(long)(mrow+8)*N + n]   = acc[j][2];
        C[(long)(mrow+8)*N + n+1] = acc[j][3];
    }
}

// ===========================================================================
// bf16 hi/lo split GEMM (3 MMAs, near-fp32). NT and TRANS variants.
// ===========================================================================
#define SA_H   0
#define SA_L   2560
#define SB_H   5120
#define SB_L   15360
#define SMEM_BYTES 25600

template<bool TRANS_B>
__global__ __launch_bounds__(256)
void gemm_tc(const float* __restrict__ A, const float* __restrict__ B,
             float* __restrict__ C, int N, int Kin)
{
    __shared__ __align__(16) unsigned char sm[SMEM_BYTES];

    const int m0 = blockIdx.y * 32;
    const int n0 = blockIdx.x * 128;
    const int tid  = threadIdx.x;
    const int lane = tid & 31;
    const int warp = tid >> 5;
    const int mw = warp >> 2;
    const int nw = warp & 3;

    float acc[4][4];
    #pragma unroll
    for (int j = 0; j < 4; j++)
        #pragma unroll
        for (int r = 0; r < 4; r++) acc[j][r] = 0.f;

    const uint32_t aAddrH = cvta_s(sm + SA_H)
        + (mw*16 + (lane & 15))*PITCH_A + (lane >> 4)*16;
    const uint32_t aAddrL = aAddrH + (SA_L - SA_H);

    uint32_t bAddrH[2], bAddrL[2];
    if (!TRANS_B) {
        #pragma unroll
        for (int jj = 0; jj < 2; jj++) {
            uint32_t nrow = nw*32 + jj*16 + (lane & 7) + ((lane >> 4) & 1)*8;
            bAddrH[jj] = cvta_s(sm + SB_H) + nrow*PITCH_B + ((lane >> 3) & 1)*16;
            bAddrL[jj] = bAddrH[jj] + (SB_L - SB_H);
        }
    } else {
        #pragma unroll
        for (int jj = 0; jj < 2; jj++) {
            uint32_t nB = (nw*32 + jj*16)*2 + ((lane >> 4) & 1)*16;
            bAddrH[jj] = cvta_s(sm + SB_H) + (lane & 15)*PITCH_BT + nB;
            bAddrL[jj] = bAddrH[jj] + (SB_L - SB_H);
        }
    }

    for (int k0 = 0; k0 < Kin; k0 += 32) {
        {
            int m  = tid >> 3, k4 = tid & 7;
            float4 v = *(const float4*)(A + (long)(m0+m)*Kin + k0 + 4*k4);
            uint2 hi, lo; cvt_split4(v, hi, lo);
            *(uint2*)(sm + SA_H + m*PITCH_A + 8*k4) = hi;
            *(uint2*)(sm + SA_L + m*PITCH_A + 8*k4) = lo;
        }
        if (!TRANS_B) {
            #pragma unroll
            for (int p = 0; p < 4; ++p) {
                int lin = tid + p*256;
                int n = lin >> 3, k4 = lin & 7;
                float4 v = *(const float4*)(B + (long)(n0+n)*Kin + k0 + 4*k4);
                uint2 hi, lo; cvt_split4(v, hi, lo);
                *(uint2*)(sm + SB_H + n*PITCH_B + 8*k4) = hi;
                *(uint2*)(sm + SB_L + n*PITCH_B + 8*k4) = lo;
            }
        } else {
            #pragma unroll
            for (int p = 0; p < 4; ++p) {
                int lin = tid + p*256;
                int k = lin >> 5, n4 = lin & 31;
                float4 v = *(const float4*)(B + (long)(k0+k)*N + n0 + 4*n4);
                uint2 hi, lo; cvt_split4(v, hi, lo);
                *(uint2*)(sm + SB_H + k*PITCH_BT + 8*n4) = hi;
                *(uint2*)(sm + SB_L + k*PITCH_BT + 8*n4) = lo;
            }
        }
        __syncthreads();

        #pragma unroll
        for (int kt = 0; kt < 2; ++kt) {
            uint32_t ah[4], al[4];
            LDSM4(ah[0],ah[1],ah[2],ah[3], aAddrH + kt*32);
            LDSM4(al[0],al[1],al[2],al[3], aAddrL + kt*32);
            uint32_t bh[4][2], bl[4][2];
            #pragma unroll
            for (int jj = 0; jj < 2; ++jj) {
                uint32_t r0,r1,r2,r3;
                if (!TRANS_B) {
                    LDSM4(r0,r1,r2,r3, bAddrH[jj] + kt*32);
                    bh[2*jj][0]=r0; bh[2*jj][1]=r1; bh[2*jj+1][0]=r2; bh[2*jj+1][1]=r3;
                    LDSM4(r0,r1,r2,r3, bAddrL[jj] + kt*32);
                    bl[2*jj][0]=r0; bl[2*jj][1]=r1; bl[2*jj+1][0]=r2; bl[2*jj+1][1]=r3;
                } else {
                    LDSM4T(r0,r1,r2,r3, bAddrH[jj] + kt*16*PITCH_BT);
                    bh[2*jj][0]=r0; bh[2*jj][1]=r1; bh[2*jj+1][0]=r2; bh[2*jj+1][1]=r3;
                    LDSM4T(r0,r1,r2,r3, bAddrL[jj] + kt*16*PITCH_BT);
                    bl[2*jj][0]=r0; bl[2*jj][1]=r1; bl[2*jj+1][0]=r2; bl[2*jj+1][1]=r3;
                }
            }
            #pragma unroll
            for (int j = 0; j < 4; ++j) {
                MMA_BF16(acc[j], ah, bh[j][0], bh[j][1]);
                MMA_BF16(acc[j], ah, bl[j][0], bl[j][1]);
                MMA_BF16(acc[j], al, bh[j][0], bh[j][1]);
            }
        }
        __syncthreads();
    }

    const int mrow = m0 + mw*16 + (lane >> 2);
    #pragma unroll
    for (int j = 0; j < 4; ++j) {
        int n = n0 + nw*32 + j*8 + 2*(lane & 3);
        C[(long)mrow*N + n]       = acc[j][0];
        C[(long)mrow*N + n + 1]   = acc[j][1];
        C[(long)(mrow+8)*N + n]   = acc[j][2];
        C[(long)(mrow+8)*N + n+1] = acc[j][3];
    }
}

// ---------------------------------------------------------------------------
__global__ void normalize_rows(float* __restrict__ C)
{
    const int row = blockIdx.x;
    float* p = C + (long)row * DIM;
    const int t = threadIdx.x;
    float v[4]; float ss = 0.f;
    #pragma unroll
    for (int i = 0; i < 4; i++) { v[i] = p[t + i*128]; ss += v[i]*v[i]; }
    __shared__ float red[128];
    red[t] = ss; __syncthreads();
    #pragma unroll
    for (int s = 64; s > 0; s >>= 1) {
        if (t < s) red[t] += red[t+s];
        __syncthreads();
    }
    float inv = 1.f / (sqrtf(red[0]) + 1e-8f);
    #pragma unroll
    for (int i = 0; i < 4; i++) p[t + i*128] = v[i] * inv;
}

extern "C" void kernel_launch(void* const* d_in, const int* in_sizes, int n_in,
                              void* d_out, int out_size)
{
    const float* E  = (const float*)d_in[0];
    const float* T  = (const float*)d_in[1];
    const float* P  = (const float*)d_in[2];
    const float* Wq = (const float*)d_in[3];
    const float* Wk = (const float*)d_in[4];
    const float* Wv = (const float*)d_in[5];
    const float* Wo = (const float*)d_in[6];

    float* outF = (float*)d_out;
    float* outA = (float*)d_out + (long)BATCH*KTOK*DIM;

    float *pQ, *pQk, *pGp, *pG, *pWc, *pRows;
    cudaGetSymbolAddress((void**)&pQ,    g_Q);
    cudaGetSymbolAddress((void**)&pQk,   g_Qk);
    cudaGetSymbolAddress((void**)&pGp,   g_Gp);
    cudaGetSymbolAddress((void**)&pG,    g_G);
    cudaGetSymbolAddress((void**)&pWc,   g_Wc);
    cudaGetSymbolAddress((void**)&pRows, g_rows);

    cudaFuncSetAttribute(fused_attn2,
        cudaFuncAttributeMaxDynamicSharedMemorySize, SMEM_FUSED);

    dim3 blk(256);

    // 1) Wcomb = Wo @ Wv : [512,512], Kin=256 (bf16 hi/lo, B=[Kin,N] trans)
    gemm_tc<true><<<dim3(DIM/128, DIM/32), blk>>>(Wo, Wv, pWc, DIM, DHEAD);

    // 2) Q = T @ Wq^T  (fp16 single)
    gemm_h<false><<<dim3(DHEAD/128, 16), blk>>>(T, Wq, pQ, DHEAD, DIM);

    // 3) Qk = Q @ Wk  (fp16 single, trans)
    gemm_h<true><<<dim3(DIM/128, 16), blk>>>(pQ, Wk, pQk, DIM, DHEAD);

    // 4) FUSED: expS/A + row sums + G partials + barrier + G reduce + A scale
    fused_attn2<<<dim3(SPLITS, BATCH), blk, SMEM_FUSED>>>(
        pQk, E, P, outA, pGp, pG, pRows);

    // 5) outF = G @ Wcomb^T  (bf16 hi/lo, B=[N,Kin] non-trans)
    gemm_tc<false><<<dim3(DIM/128, 16), blk>>>(pG, pWc, outF, DIM, DIM);

    // 6) L2-normalize outF rows
    normalize_rows<<<BATCH*KTOK, 128>>>(outF);
}

// round 7
// speedup vs baseline: 1.0227x; 1.0227x over previous
#include <cuda_runtime.h>
#include <cuda_bf16.h>
#include <cuda_fp16.h>
#include <math.h>
#include <stdint.h>

// Problem constants
#define BATCH 16
#define NPATCH 4096
#define KTOK 32
#define DIM 512
#define DHEAD 256
#define SCALE_V 0.0625f   // 256^-0.5

#define SPLITS 16         // grid = 16 x 16 = 256 blocks, occ 2 -> one wave

// Scratch (no allocation allowed -> device globals)
__device__ float  g_Q   [BATCH*KTOK*DHEAD];
__device__ __half g_Qkh [BATCH*KTOK*DIM];
__device__ float  g_Gp  [SPLITS*BATCH*KTOK*DIM];
__device__ float  g_G   [BATCH*KTOK*DIM];
__device__ float  g_F   [BATCH*KTOK*DHEAD];
__device__ float  g_rows[BATCH*KTOK*SPLITS];

// ---------------------------------------------------------------------------

#define LDSM4(R0,R1,R2,R3,ADDR) \
    asm volatile("ldmatrix.sync.aligned.m8n8.x4.shared.b16 {%0,%1,%2,%3}, [%4];" \
        : "=r"(R0),"=r"(R1),"=r"(R2),"=r"(R3) : "r"(ADDR))

#define LDSM4T(R0,R1,R2,R3,ADDR) \
    asm volatile("ldmatrix.sync.aligned.m8n8.x4.trans.shared.b16 {%0,%1,%2,%3}, [%4];" \
        : "=r"(R0),"=r"(R1),"=r"(R2),"=r"(R3) : "r"(ADDR))

#define MMA_BF16(C,A,B0,B1) \
    asm volatile("mma.sync.aligned.m16n8k16.row.col.f32.bf16.bf16.f32 " \
        "{%0,%1,%2,%3},{%4,%5,%6,%7},{%8,%9},{%0,%1,%2,%3};" \
        : "+f"((C)[0]),"+f"((C)[1]),"+f"((C)[2]),"+f"((C)[3]) \
        : "r"((A)[0]),"r"((A)[1]),"r"((A)[2]),"r"((A)[3]),"r"(B0),"r"(B1))

#define MMA_F16(C,A,B0,B1) \
    asm volatile("mma.sync.aligned.m16n8k16.row.col.f32.f16.f16.f32 " \
        "{%0,%1,%2,%3},{%4,%5,%6,%7},{%8,%9},{%0,%1,%2,%3};" \
        : "+f"((C)[0]),"+f"((C)[1]),"+f"((C)[2]),"+f"((C)[3]) \
        : "r"((A)[0]),"r"((A)[1]),"r"((A)[2]),"r"((A)[3]),"r"(B0),"r"(B1))

__device__ __forceinline__ uint32_t cvta_s(const void* p) {
    return (uint32_t)__cvta_generic_to_shared(p);
}

__device__ __forceinline__ uint2 cvt_h4(float4 v) {
    __half2 h0 = __floats2half2_rn(v.x, v.y);
    __half2 h1 = __floats2half2_rn(v.z, v.w);
    uint2 r; r.x = *(uint32_t*)&h0; r.y = *(uint32_t*)&h1; return r;
}

__device__ __forceinline__ void cvt_split4(float4 v, uint2 &hi, uint2 &lo) {
    __nv_bfloat162 h0 = __floats2bfloat162_rn(v.x, v.y);
    __nv_bfloat162 h1 = __floats2bfloat162_rn(v.z, v.w);
    float rx = v.x - __bfloat162float(h0.x);
    float ry = v.y - __bfloat162float(h0.y);
    float rz = v.z - __bfloat162float(h1.x);
    float rw = v.w - __bfloat162float(h1.y);
    __nv_bfloat162 l0 = __floats2bfloat162_rn(rx, ry);
    __nv_bfloat162 l1 = __floats2bfloat162_rn(rz, rw);
    hi.x = *(uint32_t*)&h0; hi.y = *(uint32_t*)&h1;
    lo.x = *(uint32_t*)&l0; lo.y = *(uint32_t*)&l1;
}

// ===========================================================================
// FUSED attention kernel v3 (fixed Qk staging). Block = (sp, b), 256 thr, occ 2.
// 8 chunks of 32 E-rows, DOUBLE-BUFFERED:
//   top of iter c: stage chunk c+1 into other buffer (overlaps compute)
//   phase1: S[32,32] = Qk_res @ Echunk^T -> exp -> A(unnorm) + expS smem
//   phase2: accG[32,512] += expS @ Echunk
// End: Gp partial + row-sum partials. Reduction/scale in post kernel.
// ===========================================================================
#define QK_OFF   0
#define QK_PITCH 1040
#define E0_OFF   33280
#define E_BUF    33280         // bytes per E buffer (32*1040)
#define E_PITCH  1040
#define ES_OFF   99840         // E0_OFF + 2*E_BUF
#define ES_PITCH 80            // 32 fp16 + 8 pad (16B-aligned rows)
#define RED_OFF  102400        // ES_OFF + 32*80
#define SMEM_FUSED 102912

__global__ __launch_bounds__(256, 2)
void fused_attn3(const __half* __restrict__ Qkh, const float* __restrict__ E,
                 const float* __restrict__ P, float* __restrict__ outA,
                 float* __restrict__ Gp, float* __restrict__ rows)
{
    extern __shared__ __align__(16) unsigned char sm[];
    const int sp = blockIdx.x;         // 0..15
    const int b  = blockIdx.y;         // 0..15
    const int tid  = threadIdx.x;
    const int lane = tid & 31;
    const int warp = tid >> 5;
    const int mw = warp >> 2;          // 0..1
    const int nw = warp & 3;           // 0..3

    const float*  Eb   = E   + (long)b*NPATCH*DIM;
    const __half* Qkb  = Qkh + (long)b*KTOK*DIM;
    const float*  Pb   = P   + (long)b*NPATCH;
    float*        Ab   = outA + (long)b*KTOK*NPATCH;

    // resident Qk [32,512] fp16 (raw copy; 64 x uint4 per row)  [BUGFIX]
    #pragma unroll
    for (int p = 0; p < 8; ++p) {
        int lin = tid + p*256;
        int r = lin >> 6, seg = lin & 63;       // 64 x 16B per row
        uint4 v = *(const uint4*)(Qkb + r*DIM + seg*8);
        *(uint4*)(sm + QK_OFF + r*QK_PITCH + seg*16) = v;
    }

    float accG[16][4];
    #pragma unroll
    for (int t2 = 0; t2 < 16; ++t2)
        #pragma unroll
        for (int r = 0; r < 4; ++r) accG[t2][r] = 0.f;
    float rsum0 = 0.f, rsum8 = 0.f;

    const uint32_t smb = cvta_s(sm);
    const uint32_t aQkBase = smb + QK_OFF + (mw*16 + (lane & 15))*QK_PITCH + (lane >> 4)*16;
    // phase1 B: n8 per warp; x4 covers k32 (4 k8-tiles along the row)
    const uint32_t b1Off = (nw*8 + (lane & 7))*E_PITCH + (lane >> 3)*16;
    // phase2 A: expS m16 x k16 tiles
    const uint32_t aEsBase = smb + ES_OFF + (mw*16 + (lane & 15))*ES_PITCH + (lane >> 4)*16;
    // phase2 B: trans, k16 rows x n16 cols per LDSM4T
    const uint32_t b2Off = (lane & 15)*E_PITCH + nw*256 + ((lane >> 4) & 1)*16;

    const int nbase = sp * (NPATCH/SPLITS);   // 256-row slice

    // ---- stage chunk 0 into buffer 0 ----
    {
        const float* src = Eb + (long)nbase*DIM;
        #pragma unroll 8
        for (int p = 0; p < 16; ++p) {
            int lin = tid + p*256;
            int r = lin >> 7, c4 = lin & 127;
            float4 v = *(const float4*)(src + (long)r*DIM + 4*c4);
            *(uint2*)(sm + E0_OFF + r*E_PITCH + 8*c4) = cvt_h4(v);
        }
    }
    __syncthreads();

    for (int c = 0; c < 8; ++c) {
        const int n0 = nbase + c*32;
        const uint32_t bufc = E0_OFF + (c & 1)*E_BUF;
        const uint32_t bufn = E0_OFF + ((c+1) & 1)*E_BUF;

        // ---- stage chunk c+1 into the other buffer (overlaps compute) ----
        if (c < 7) {
            const float* src = Eb + (long)(n0 + 32)*DIM;
            #pragma unroll 8
            for (int p = 0; p < 16; ++p) {
                int lin = tid + p*256;
                int r = lin >> 7, c4 = lin & 127;
                float4 v = *(const float4*)(src + (long)r*DIM + 4*c4);
                *(uint2*)(sm + bufn + r*E_PITCH + 8*c4) = cvt_h4(v);
            }
        }

        // ---- phase 1: S[32,32] = Qk @ Echunk^T ----
        float sacc[4] = {0.f, 0.f, 0.f, 0.f};
        const uint32_t b1 = smb + bufc + b1Off;
        #pragma unroll
        for (int ks = 0; ks < 16; ++ks) {      // k32 per step
            uint32_t bf[4];
            LDSM4(bf[0],bf[1],bf[2],bf[3], b1 + ks*64);
            uint32_t a0[4];
            LDSM4(a0[0],a0[1],a0[2],a0[3], aQkBase + ks*64);
            MMA_F16(sacc, a0, bf[0], bf[1]);
            uint32_t a1[4];
            LDSM4(a1[0],a1[1],a1[2],a1[3], aQkBase + ks*64 + 32);
            MMA_F16(sacc, a1, bf[2], bf[3]);
        }

        // ---- epilogue: exp + A(unnorm) + expS smem + row sums ----
        {
            const int mrow = mw*16 + (lane >> 2);
            int nl = nw*8 + 2*(lane & 3);
            int gn = n0 + nl;
            float lp0 = __logf(fminf(fmaxf(Pb[gn],   0.1f), 0.9f));
            float lp1 = __logf(fminf(fmaxf(Pb[gn+1], 0.1f), 0.9f));
            float v0 = __expf(sacc[0]*SCALE_V + lp0);
            float v1 = __expf(sacc[1]*SCALE_V + lp1);
            float v2 = __expf(sacc[2]*SCALE_V + lp0);
            float v3 = __expf(sacc[3]*SCALE_V + lp1);
            rsum0 += v0 + v1; rsum8 += v2 + v3;
            *(float2*)(Ab + (long)mrow*NPATCH + gn)     = make_float2(v0, v1);
            *(float2*)(Ab + (long)(mrow+8)*NPATCH + gn) = make_float2(v2, v3);
            __half2 h01 = __floats2half2_rn(v0, v1);
            __half2 h23 = __floats2half2_rn(v2, v3);
            *(uint32_t*)(sm + ES_OFF + mrow*ES_PITCH + nl*2)     = *(uint32_t*)&h01;
            *(uint32_t*)(sm + ES_OFF + (mrow+8)*ES_PITCH + nl*2) = *(uint32_t*)&h23;
        }
        __syncthreads();   // ES + staged bufn visible

        // ---- phase 2: accG += expS[32,32] @ Echunk[32,512] ----
        const uint32_t b2 = smb + bufc + b2Off;
        #pragma unroll
        for (int ks = 0; ks < 2; ++ks) {       // k16 steps
            uint32_t a[4];
            LDSM4(a[0],a[1],a[2],a[3], aEsBase + ks*32);
            #pragma unroll
            for (int jt = 0; jt < 8; ++jt) {
                uint32_t r0,r1,r2,r3;
                LDSM4T(r0,r1,r2,r3, b2 + ks*16*E_PITCH + jt*32);
                MMA_F16(accG[2*jt],   a, r0, r1);
                MMA_F16(accG[2*jt+1], a, r2, r3);
            }
        }
        __syncthreads();   // bufc + ES free for reuse
    }

    // ---- write G partial ----
    {
        float* Gpb = Gp + ((long)(b*SPLITS + sp)*KTOK)*DIM;
        const int mrow = mw*16 + (lane >> 2);
        #pragma unroll
        for (int t2 = 0; t2 < 16; ++t2) {
            int d = nw*128 + t2*8 + 2*(lane & 3);
            *(float2*)(Gpb + (long)mrow*DIM + d)     = make_float2(accG[t2][0], accG[t2][1]);
            *(float2*)(Gpb + (long)(mrow+8)*DIM + d) = make_float2(accG[t2][2], accG[t2][3]);
        }
    }

    // ---- row-sum partials ----
    rsum0 += __shfl_xor_sync(0xffffffffu, rsum0, 1);
    rsum0 += __shfl_xor_sync(0xffffffffu, rsum0, 2);
    rsum8 += __shfl_xor_sync(0xffffffffu, rsum8, 1);
    rsum8 += __shfl_xor_sync(0xffffffffu, rsum8, 2);
    {
        float (*srow)[4] = (float(*)[4])(sm + RED_OFF);
        if ((lane & 3) == 0) {
            srow[mw*16 + (lane >> 2)][nw]     = rsum0;
            srow[mw*16 + 8 + (lane >> 2)][nw] = rsum8;
        }
        __syncthreads();
        if (tid < 32) {
            float s = srow[tid][0] + srow[tid][1] + srow[tid][2] + srow[tid][3];
            rows[(b*KTOK + tid)*SPLITS + sp] = s;
        }
    }
}

// ===========================================================================
// post kernel: blocks [0,256) reduce G partials; blocks [256,768) scale A rows.
// ===========================================================================
__global__ __launch_bounds__(256)
void post_kernel(const float* __restrict__ Gp, float* __restrict__ G,
                 const float* __restrict__ rows, float* __restrict__ A)
{
    if (blockIdx.x < 256) {
        int i = blockIdx.x*256 + threadIdx.x;        // float4 index, 65536 total
        int bb  = i >> 12;                           // 4096 float4 per batch
        int rem = i & 4095;
        const float4* p = (const float4*)Gp + ((long)bb*SPLITS)*4096 + rem;
        float4 s = make_float4(0.f, 0.f, 0.f, 0.f);
        #pragma unroll
        for (int s2 = 0; s2 < SPLITS; ++s2) {
            float4 v = p[(long)s2*4096];
            s.x += v.x; s.y += v.y; s.z += v.z; s.w += v.w;
        }
        ((float4*)G)[i] = s;
    } else {
        int r = blockIdx.x - 256;                    // 0..511 (b*32+k)
        float s = 0.f;
        #pragma unroll
        for (int c = 0; c < SPLITS; ++c) s += rows[r*SPLITS + c];
        float inv = 1.f / s;
        float4* pa = (float4*)(A + (long)r*NPATCH);
        #pragma unroll
        for (int q = 0; q < 4; ++q) {
            int idx = threadIdx.x + q*256;
            float4 v = pa[idx];
            v.x *= inv; v.y *= inv; v.z *= inv; v.w *= inv;
            pa[idx] = v;
        }
    }
}

// ===========================================================================
// fp16 single-MMA GEMM for projections. BM=32, BN=128, BK=32, 256 thr.
// HALF_OUT: write fp16 output (for Qk feeding fused).
// ===========================================================================
#define PITCH_A   80
#define PITCH_B   80
#define PITCH_BT  272
#define HS_A 0
#define HS_B 2560
#define HS_BYTES (2560 + 10240)

template<bool TRANS_B, bool HALF_OUT>
__global__ __launch_bounds__(256)
void gemm_h(const float* __restrict__ A, const float* __restrict__ B,
            void* __restrict__ Cv, int N, int Kin)
{
    __shared__ __align__(16) unsigned char sm[HS_BYTES];

    const int m0 = blockIdx.y * 32;
    const int n0 = blockIdx.x * 128;
    const int tid  = threadIdx.x;
    const int lane = tid & 31;
    const int warp = tid >> 5;
    const int mw = warp >> 2;
    const int nw = warp & 3;

    float acc[4][4];
    #pragma unroll
    for (int j = 0; j < 4; j++)
        #pragma unroll
        for (int r = 0; r < 4; r++) acc[j][r] = 0.f;

    const uint32_t aAddr = cvta_s(sm + HS_A)
        + (mw*16 + (lane & 15))*PITCH_A + (lane >> 4)*16;
    uint32_t bAddr[2];
    if (!TRANS_B) {
        #pragma unroll
        for (int jj = 0; jj < 2; jj++) {
            uint32_t nrow = nw*32 + jj*16 + (lane & 7) + ((lane >> 4) & 1)*8;
            bAddr[jj] = cvta_s(sm + HS_B) + nrow*PITCH_B + ((lane >> 3) & 1)*16;
        }
    } else {
        #pragma unroll
        for (int jj = 0; jj < 2; jj++) {
            uint32_t nB = (nw*32 + jj*16)*2 + ((lane >> 4) & 1)*16;
            bAddr[jj] = cvta_s(sm + HS_B) + (lane & 15)*PITCH_BT + nB;
        }
    }

    const int am  = tid >> 3, ak4 = tid & 7;
    const float* aG = A + (long)(m0 + am)*Kin + 4*ak4;

    float4 pa, pb[4];
    pa = *(const float4*)(aG);
    if (!TRANS_B) {
        #pragma unroll
        for (int p = 0; p < 4; ++p) {
            int lin = tid + p*256;
            pb[p] = *(const float4*)(B + (long)(n0 + (lin >> 3))*Kin + 4*(lin & 7));
        }
    } else {
        #pragma unroll
        for (int p = 0; p < 4; ++p) {
            int lin = tid + p*256;
            pb[p] = *(const float4*)(B + (long)(lin >> 5)*N + n0 + 4*(lin & 31));
        }
    }

    for (int k0 = 0; k0 < Kin; k0 += 32) {
        *(uint2*)(sm + HS_A + am*PITCH_A + 8*ak4) = cvt_h4(pa);
        if (!TRANS_B) {
            #pragma unroll
            for (int p = 0; p < 4; ++p) {
                int lin = tid + p*256;
                *(uint2*)(sm + HS_B + (lin >> 3)*PITCH_B + 8*(lin & 7)) = cvt_h4(pb[p]);
            }
        } else {
            #pragma unroll
            for (int p = 0; p < 4; ++p) {
                int lin = tid + p*256;
                *(uint2*)(sm + HS_B + (lin >> 5)*PITCH_BT + 8*(lin & 31)) = cvt_h4(pb[p]);
            }
        }
        __syncthreads();

        int kn = k0 + 32;
        if (kn < Kin) {
            pa = *(const float4*)(aG + kn);
            if (!TRANS_B) {
                #pragma unroll
                for (int p = 0; p < 4; ++p) {
                    int lin = tid + p*256;
                    pb[p] = *(const float4*)(B + (long)(n0 + (lin >> 3))*Kin + kn + 4*(lin & 7));
                }
            } else {
                #pragma unroll
                for (int p = 0; p < 4; ++p) {
                    int lin = tid + p*256;
                    pb[p] = *(const float4*)(B + (long)(kn + (lin >> 5))*N + n0 + 4*(lin & 31));
                }
            }
        }

        #pragma unroll
        for (int kt = 0; kt < 2; ++kt) {
            uint32_t a[4];
            LDSM4(a[0],a[1],a[2],a[3], aAddr + kt*32);
            uint32_t bf[4][2];
            #pragma unroll
            for (int jj = 0; jj < 2; ++jj) {
                uint32_t r0,r1,r2,r3;
                if (!TRANS_B) {
                    LDSM4(r0,r1,r2,r3, bAddr[jj] + kt*32);
                } else {
                    LDSM4T(r0,r1,r2,r3, bAddr[jj] + kt*16*PITCH_BT);
                }
                bf[2*jj][0]=r0; bf[2*jj][1]=r1; bf[2*jj+1][0]=r2; bf[2*jj+1][1]=r3;
            }
            #pragma unroll
            for (int j = 0; j < 4; ++j)
                MMA_F16(acc[j], a, bf[j][0], bf[j][1]);
        }
        __syncthreads();
    }

    const int mrow = m0 + mw*16 + (lane >> 2);
    if (HALF_OUT) {
        __half* C = (__half*)Cv;
        #pragma unroll
        for (int j = 0; j < 4; ++j) {
            int n = n0 + nw*32 + j*8 + 2*(lane & 3);
            __half2 h01 = __floats2half2_rn(acc[j][0], acc[j][1]);
            __half2 h23 = __floats2half2_rn(acc[j][2], acc[j][3]);
            *(uint32_t*)(C + (long)mrow*N + n)     = *(uint32_t*)&h01;
            *(uint32_t*)(C + (long)(mrow+8)*N + n) = *(uint32_t*)&h23;
        }
    } else {
        float* C = (float*)Cv;
        #pragma unroll
        for (int j = 0; j < 4; ++j) {
            int n = n0 + nw*32 + j*8 + 2*(lane & 3);
            C[(long)mrow*N + n]       = acc[j][0];
            C[(long)mrow*N + n + 1]   = acc[j][1];
            C[(long)(mrow+8)*N + n]   = acc[j][2];
            C[(long)(mrow+8)*N + n+1] = acc[j][3];
        }
    }
}

// ===========================================================================
// bf16 hi/lo split GEMM (3 MMAs, near-fp32). B = [N,Kin] row-major (NT).
// ===========================================================================
#define SA_H   0
#define SA_L   2560
#define SB_H   5120
#define SB_L   15360
#define SMEM_BYTES 25600

__global__ __launch_bounds__(256)
void gemm_tc_nt(const float* __restrict__ A, const float* __restrict__ B,
                float* __restrict__ C, int N, int Kin)
{
    __shared__ __align__(16) unsigned char sm[SMEM_BYTES];

    const int m0 = blockIdx.y * 32;
    const int n0 = blockIdx.x * 128;
    const int tid  = threadIdx.x;
    const int lane = tid & 31;
    const int warp = tid >> 5;
    const int mw = warp >> 2;
    const int nw = warp & 3;

    float acc[4][4];
    #pragma unroll
    for (int j = 0; j < 4; j++)
        #pragma unroll
        for (int r = 0; r < 4; r++) acc[j][r] = 0.f;

    const uint32_t aAddrH = cvta_s(sm + SA_H)
        + (mw*16 + (lane & 15))*PITCH_A + (lane >> 4)*16;
    const uint32_t aAddrL = aAddrH + (SA_L - SA_H);

    uint32_t bAddrH[2], bAddrL[2];
    #pragma unroll
    for (int jj = 0; jj < 2; jj++) {
        uint32_t nrow = nw*32 + jj*16 + (lane & 7) + ((lane >> 4) & 1)*8;
        bAddrH[jj] = cvta_s(sm + SB_H) + nrow*PITCH_B + ((lane >> 3) & 1)*16;
        bAddrL[jj] = bAddrH[jj] + (SB_L - SB_H);
    }

    for (int k0 = 0; k0 < Kin; k0 += 32) {
        {
            int m  = tid >> 3, k4 = tid & 7;
            float4 v = *(const float4*)(A + (long)(m0+m)*Kin + k0 + 4*k4);
            uint2 hi, lo; cvt_split4(v, hi, lo);
            *(uint2*)(sm + SA_H + m*PITCH_A + 8*k4) = hi;
            *(uint2*)(sm + SA_L + m*PITCH_A + 8*k4) = lo;
        }
        #pragma unroll
        for (int p = 0; p < 4; ++p) {
            int lin = tid + p*256;
            int n = lin >> 3, k4 = lin & 7;
            float4 v = *(const float4*)(B + (long)(n0+n)*Kin + k0 + 4*k4);
            uint2 hi, lo; cvt_split4(v, hi, lo);
            *(uint2*)(sm + SB_H + n*PITCH_B + 8*k4) = hi;
            *(uint2*)(sm + SB_L + n*PITCH_B + 8*k4) = lo;
        }
        __syncthreads();

        #pragma unroll
        for (int kt = 0; kt < 2; ++kt) {
            uint32_t ah[4], al[4];
            LDSM4(ah[0],ah[1],ah[2],ah[3], aAddrH + kt*32);
            LDSM4(al[0],al[1],al[2],al[3], aAddrL + kt*32);
            uint32_t bh[4][2], bl[4][2];
            #pragma unroll
            for (int jj = 0; jj < 2; ++jj) {
                uint32_t r0,r1,r2,r3;
                LDSM4(r0,r1,r2,r3, bAddrH[jj] + kt*32);
                bh[2*jj][0]=r0; bh[2*jj][1]=r1; bh[2*jj+1][0]=r2; bh[2*jj+1][1]=r3;
                LDSM4(r0,r1,r2,r3, bAddrL[jj] + kt*32);
                bl[2*jj][0]=r0; bl[2*jj][1]=r1; bl[2*jj+1][0]=r2; bl[2*jj+1][1]=r3;
            }
            #pragma unroll
            for (int j = 0; j < 4; ++j) {
                MMA_BF16(acc[j], ah, bh[j][0], bh[j][1]);
                MMA_BF16(acc[j], ah, bl[j][0], bl[j][1]);
                MMA_BF16(acc[j], al, bh[j][0], bh[j][1]);
            }
        }
        __syncthreads();
    }

    const int mrow = m0 + mw*16 + (lane >> 2);
    #pragma unroll
    for (int j = 0; j < 4; ++j) {
        int n = n0 + nw*32 + j*8 + 2*(lane & 3);
        C[(long)mrow*N + n]       = acc[j][0];
        C[(long)mrow*N + n + 1]   = acc[j][1];
        C[(long)(mrow+8)*N + n]   = acc[j][2];
        C[(long)(mrow+8)*N + n+1] = acc[j][3];
    }
}

// ---------------------------------------------------------------------------
__global__ void normalize_rows(float* __restrict__ C)
{
    const int row = blockIdx.x;
    float* p = C + (long)row * DIM;
    const int t = threadIdx.x;
    float v[4]; float ss = 0.f;
    #pragma unroll
    for (int i = 0; i < 4; i++) { v[i] = p[t + i*128]; ss += v[i]*v[i]; }
    __shared__ float red[128];
    red[t] = ss; __syncthreads();
    #pragma unroll
    for (int s = 64; s > 0; s >>= 1) {
        if (t < s) red[t] += red[t+s];
        __syncthreads();
    }
    float inv = 1.f / (sqrtf(red[0]) + 1e-8f);
    #pragma unroll
    for (int i = 0; i < 4; i++) p[t + i*128] = v[i] * inv;
}

extern "C" void kernel_launch(void* const* d_in, const int* in_sizes, int n_in,
                              void* d_out, int out_size)
{
    const float* E  = (const float*)d_in[0];
    const float* T  = (const float*)d_in[1];
    const float* P  = (const float*)d_in[2];
    const float* Wq = (const float*)d_in[3];
    const float* Wk = (const float*)d_in[4];
    const float* Wv = (const float*)d_in[5];
    const float* Wo = (const float*)d_in[6];

    float* outF = (float*)d_out;
    float* outA = (float*)d_out + (long)BATCH*KTOK*DIM;

    float *pQ, *pGp, *pG, *pF, *pRows;
    __half* pQkh;
    cudaGetSymbolAddress((void**)&pQ,    g_Q);
    cudaGetSymbolAddress((void**)&pQkh,  g_Qkh);
    cudaGetSymbolAddress((void**)&pGp,   g_Gp);
    cudaGetSymbolAddress((void**)&pG,    g_G);
    cudaGetSymbolAddress((void**)&pF,    g_F);
    cudaGetSymbolAddress((void**)&pRows, g_rows);

    cudaFuncSetAttribute(fused_attn3,
        cudaFuncAttributeMaxDynamicSharedMemorySize, SMEM_FUSED);

    dim3 blk(256);

    // 1) Q = T @ Wq^T  (fp16 single, fp32 out)
    gemm_h<false,false><<<dim3(DHEAD/128, 16), blk>>>(T, Wq, pQ, DHEAD, DIM);

    // 2) Qk = Q @ Wk  (fp16 single, trans, fp16 out)
    gemm_h<true,true><<<dim3(DIM/128, 16), blk>>>(pQ, Wk, pQkh, DIM, DHEAD);

    // 3) FUSED: expS/A(unnorm) + row-sum partials + G partials
    fused_attn3<<<dim3(SPLITS, BATCH), blk, SMEM_FUSED>>>(
        pQkh, E, P, outA, pGp, pRows);

    // 4) post: G reduce (256 blocks) + A row-scale (512 blocks)
    post_kernel<<<768, blk>>>(pGp, pG, pRows, outA);

    // 5) F = G @ Wv^T  (bf16 hi/lo)
    gemm_tc_nt<<<dim3(DHEAD/128, 16), blk>>>(pG, Wv, pF, DHEAD, DIM);

    // 6) out = F @ Wo^T  (bf16 hi/lo)
    gemm_tc_nt<<<dim3(DIM/128, 16), blk>>>(pF, Wo, outF, DIM, DHEAD);

    // 7) L2-normalize outF rows
    normalize_rows<<<BATCH*KTOK, 128>>>(outF);
}

// round 8
// speedup vs baseline: 1.0830x; 1.0590x over previous
#include <cuda_runtime.h>
#include <cuda_bf16.h>
#include <cuda_fp16.h>
#include <math.h>
#include <stdint.h>

// Problem constants
#define BATCH 16
#define NPATCH 4096
#define KTOK 32
#define DIM 512
#define DHEAD 256
#define SCALE_V 0.0625f   // 256^-0.5

#define SPLITS 16         // grid = 16 x 16 = 256 blocks, occ 2

// Scratch (no allocation allowed -> device globals)
__device__ __half g_Qkh [BATCH*KTOK*DIM];
__device__ float  g_Gp  [SPLITS*BATCH*KTOK*DIM];
__device__ float  g_G   [BATCH*KTOK*DIM];
__device__ float  g_F   [BATCH*KTOK*DHEAD];
__device__ float  g_rows[BATCH*KTOK*SPLITS];

// ---------------------------------------------------------------------------

#define LDSM4(R0,R1,R2,R3,ADDR) \
    asm volatile("ldmatrix.sync.aligned.m8n8.x4.shared.b16 {%0,%1,%2,%3}, [%4];" \
        : "=r"(R0),"=r"(R1),"=r"(R2),"=r"(R3) : "r"(ADDR))

#define LDSM4T(R0,R1,R2,R3,ADDR) \
    asm volatile("ldmatrix.sync.aligned.m8n8.x4.trans.shared.b16 {%0,%1,%2,%3}, [%4];" \
        : "=r"(R0),"=r"(R1),"=r"(R2),"=r"(R3) : "r"(ADDR))

#define MMA_BF16(C,A,B0,B1) \
    asm volatile("mma.sync.aligned.m16n8k16.row.col.f32.bf16.bf16.f32 " \
        "{%0,%1,%2,%3},{%4,%5,%6,%7},{%8,%9},{%0,%1,%2,%3};" \
        : "+f"((C)[0]),"+f"((C)[1]),"+f"((C)[2]),"+f"((C)[3]) \
        : "r"((A)[0]),"r"((A)[1]),"r"((A)[2]),"r"((A)[3]),"r"(B0),"r"(B1))

#define MMA_F16(C,A,B0,B1) \
    asm volatile("mma.sync.aligned.m16n8k16.row.col.f32.f16.f16.f32 " \
        "{%0,%1,%2,%3},{%4,%5,%6,%7},{%8,%9},{%0,%1,%2,%3};" \
        : "+f"((C)[0]),"+f"((C)[1]),"+f"((C)[2]),"+f"((C)[3]) \
        : "r"((A)[0]),"r"((A)[1]),"r"((A)[2]),"r"((A)[3]),"r"(B0),"r"(B1))

__device__ __forceinline__ uint32_t cvta_s(const void* p) {
    return (uint32_t)__cvta_generic_to_shared(p);
}

__device__ __forceinline__ uint2 cvt_h4(float4 v) {
    __half2 h0 = __floats2half2_rn(v.x, v.y);
    __half2 h1 = __floats2half2_rn(v.z, v.w);
    uint2 r; r.x = *(uint32_t*)&h0; r.y = *(uint32_t*)&h1; return r;
}

__device__ __forceinline__ void cvt_split4(float4 v, uint2 &hi, uint2 &lo) {
    __nv_bfloat162 h0 = __floats2bfloat162_rn(v.x, v.y);
    __nv_bfloat162 h1 = __floats2bfloat162_rn(v.z, v.w);
    float rx = v.x - __bfloat162float(h0.x);
    float ry = v.y - __bfloat162float(h0.y);
    float rz = v.z - __bfloat162float(h1.x);
    float rw = v.w - __bfloat162float(h1.y);
    __nv_bfloat162 l0 = __floats2bfloat162_rn(rx, ry);
    __nv_bfloat162 l1 = __floats2bfloat162_rn(rz, rw);
    hi.x = *(uint32_t*)&h0; hi.y = *(uint32_t*)&h1;
    lo.x = *(uint32_t*)&l0; lo.y = *(uint32_t*)&l1;
}

// ===========================================================================
// FUSED attention kernel v4 (= round-5 fused_attn2 core, no barrier/post).
// Block = (split sp, batch b), 256 thr, occ 2. 4 chunks of 64 E-rows:
//   stage E[64,512] fp32->fp16 smem
//   phase1: S[32,64] = Qk_res @ Echunk^T -> exp(+logP from smem) ->
//           A(unnorm) out + expS smem + rowsum acc
//   phase2: accG[32,512] += expS @ Echunk
// End: Gp partial + rowsum partials.
// ===========================================================================
#define QK_OFF   0
#define QK_PITCH 1040
#define E_OFF    33280         // 32*1040
#define E_PITCH  1040
#define ES_OFF   99840         // E_OFF + 64*1040
#define ES_PITCH 144           // 64 fp16 + 8 pad
#define RED_OFF  104448        // ES_OFF + 32*144
#define LP_OFF   104960        // RED_OFF + 512
#define SMEM_FUSED 105984      // LP_OFF + 1024

__global__ __launch_bounds__(256, 2)
void fused_attn4(const __half* __restrict__ Qkh, const float* __restrict__ E,
                 const float* __restrict__ P, float* __restrict__ outA,
                 float* __restrict__ Gp, float* __restrict__ rows)
{
    extern __shared__ __align__(16) unsigned char sm[];
    const int sp = blockIdx.x;         // 0..15
    const int b  = blockIdx.y;         // 0..15
    const int tid  = threadIdx.x;
    const int lane = tid & 31;
    const int warp = tid >> 5;
    const int mw = warp >> 2;          // 0..1
    const int nw = warp & 3;           // 0..3

    const float*  Eb  = E   + (long)b*NPATCH*DIM;
    const __half* Qkb = Qkh + (long)b*KTOK*DIM;
    const float*  Pb  = P   + (long)b*NPATCH;
    float*        Ab  = outA + (long)b*KTOK*NPATCH;

    const int nbase = sp * (NPATCH/SPLITS);   // 256-row slice

    // resident Qk [32,512] fp16 (raw copy; 64 x 16B segs per row)
    #pragma unroll
    for (int p = 0; p < 8; ++p) {
        int lin = tid + p*256;
        int r = lin >> 6, seg = lin & 63;
        uint4 v = *(const uint4*)(Qkb + r*DIM + seg*8);
        *(uint4*)(sm + QK_OFF + r*QK_PITCH + seg*16) = v;
    }
    // precompute logP for this block's 256-col slice
    {
        float pv = Pb[nbase + tid];
        ((float*)(sm + LP_OFF))[tid] = __logf(fminf(fmaxf(pv, 0.1f), 0.9f));
    }

    float accG[16][4];
    #pragma unroll
    for (int t2 = 0; t2 < 16; ++t2)
        #pragma unroll
        for (int r = 0; r < 4; ++r) accG[t2][r] = 0.f;
    float rsum0 = 0.f, rsum8 = 0.f;

    const uint32_t smb = cvta_s(sm);
    const uint32_t aQkBase = smb + QK_OFF + (mw*16 + (lane & 15))*QK_PITCH + (lane >> 4)*16;
    const uint32_t b1Base  = smb + E_OFF
        + (nw*16 + (lane & 7) + ((lane >> 4) & 1)*8)*E_PITCH + ((lane >> 3) & 1)*16;
    const uint32_t aEsBase = smb + ES_OFF + (mw*16 + (lane & 15))*ES_PITCH + (lane >> 4)*16;
    const uint32_t b2Base  = smb + E_OFF + (lane & 15)*E_PITCH + nw*256 + ((lane >> 4) & 1)*16;
    const float* LPs = (const float*)(sm + LP_OFF);

    for (int c = 0; c < 4; ++c) {
        const int n0 = nbase + c*64;
        __syncthreads();   // protect E & expS reuse
        // ---- stage E[64,512] fp32->fp16 ----
        #pragma unroll 8
        for (int p = 0; p < 32; ++p) {
            int lin = tid + p*256;
            int r = lin >> 7, c4 = lin & 127;
            float4 v = *(const float4*)(Eb + (long)(n0 + r)*DIM + 4*c4);
            *(uint2*)(sm + E_OFF + r*E_PITCH + 8*c4) = cvt_h4(v);
        }
        __syncthreads();

        // ---- phase 1: S = Qk @ Echunk^T ----
        float sacc[2][4];
        #pragma unroll
        for (int j = 0; j < 2; ++j)
            #pragma unroll
            for (int r = 0; r < 4; ++r) sacc[j][r] = 0.f;
        #pragma unroll
        for (int ks = 0; ks < 32; ++ks) {
            uint32_t a[4], r0, r1, r2, r3;
            LDSM4(a[0],a[1],a[2],a[3], aQkBase + ks*32);
            LDSM4(r0,r1,r2,r3, b1Base + ks*32);
            MMA_F16(sacc[0], a, r0, r1);
            MMA_F16(sacc[1], a, r2, r3);
        }

        // ---- epilogue: exp + A(unnorm) out + expS smem + row sums ----
        {
            const int mrow = mw*16 + (lane >> 2);
            #pragma unroll
            for (int j = 0; j < 2; ++j) {
                int nl = nw*16 + j*8 + 2*(lane & 3);
                int gn = n0 + nl;
                float lp0 = LPs[c*64 + nl];
                float lp1 = LPs[c*64 + nl + 1];
                float v0 = __expf(sacc[j][0]*SCALE_V + lp0);
                float v1 = __expf(sacc[j][1]*SCALE_V + lp1);
                float v2 = __expf(sacc[j][2]*SCALE_V + lp0);
                float v3 = __expf(sacc[j][3]*SCALE_V + lp1);
                rsum0 += v0 + v1; rsum8 += v2 + v3;
                *(float2*)(Ab + (long)mrow*NPATCH + gn)     = make_float2(v0, v1);
                *(float2*)(Ab + (long)(mrow+8)*NPATCH + gn) = make_float2(v2, v3);
                __half2 h01 = __floats2half2_rn(v0, v1);
                __half2 h23 = __floats2half2_rn(v2, v3);
                *(uint32_t*)(sm + ES_OFF + mrow*ES_PITCH + nl*2)     = *(uint32_t*)&h01;
                *(uint32_t*)(sm + ES_OFF + (mrow+8)*ES_PITCH + nl*2) = *(uint32_t*)&h23;
            }
        }
        __syncthreads();

        // ---- phase 2: accG += expS[32,64] @ Echunk[64,512] ----
        #pragma unroll
        for (int ks = 0; ks < 4; ++ks) {
            uint32_t a[4];
            LDSM4(a[0],a[1],a[2],a[3], aEsBase + ks*32);
            #pragma unroll
            for (int jt = 0; jt < 8; ++jt) {
                uint32_t r0, r1, r2, r3;
                LDSM4T(r0,r1,r2,r3, b2Base + ks*16*E_PITCH + jt*32);
                MMA_F16(accG[2*jt],   a, r0, r1);
                MMA_F16(accG[2*jt+1], a, r2, r3);
            }
        }
    }

    // ---- write G partial ----
    {
        float* Gpb = Gp + ((long)(b*SPLITS + sp)*KTOK)*DIM;
        const int mrow = mw*16 + (lane >> 2);
        #pragma unroll
        for (int t2 = 0; t2 < 16; ++t2) {
            int d = nw*128 + t2*8 + 2*(lane & 3);
            *(float2*)(Gpb + (long)mrow*DIM + d)     = make_float2(accG[t2][0], accG[t2][1]);
            *(float2*)(Gpb + (long)(mrow+8)*DIM + d) = make_float2(accG[t2][2], accG[t2][3]);
        }
    }

    // ---- row-sum partials ----
    rsum0 += __shfl_xor_sync(0xffffffffu, rsum0, 1);
    rsum0 += __shfl_xor_sync(0xffffffffu, rsum0, 2);
    rsum8 += __shfl_xor_sync(0xffffffffu, rsum8, 1);
    rsum8 += __shfl_xor_sync(0xffffffffu, rsum8, 2);
    {
        float (*srow)[4] = (float(*)[4])(sm + RED_OFF);
        __syncthreads();
        if ((lane & 3) == 0) {
            srow[mw*16 + (lane >> 2)][nw]     = rsum0;
            srow[mw*16 + 8 + (lane >> 2)][nw] = rsum8;
        }
        __syncthreads();
        if (tid < 32) {
            float s = srow[tid][0] + srow[tid][1] + srow[tid][2] + srow[tid][3];
            rows[(b*KTOK + tid)*SPLITS + sp] = s;
        }
    }
}

// ===========================================================================
// post kernel: blocks [0,256) reduce G partials; blocks [256,768) scale A rows.
// ===========================================================================
__global__ __launch_bounds__(256)
void post_kernel(const float* __restrict__ Gp, float* __restrict__ G,
                 const float* __restrict__ rows, float* __restrict__ A)
{
    if (blockIdx.x < 256) {
        int i = blockIdx.x*256 + threadIdx.x;        // float4 index, 65536 total
        int bb  = i >> 12;                           // 4096 float4 per batch
        int rem = i & 4095;
        const float4* p = (const float4*)Gp + ((long)bb*SPLITS)*4096 + rem;
        float4 s = make_float4(0.f, 0.f, 0.f, 0.f);
        #pragma unroll
        for (int s2 = 0; s2 < SPLITS; ++s2) {
            float4 v = p[(long)s2*4096];
            s.x += v.x; s.y += v.y; s.z += v.z; s.w += v.w;
        }
        ((float4*)G)[i] = s;
    } else {
        int r = blockIdx.x - 256;                    // 0..511 (b*32+k)
        float s = 0.f;
        #pragma unroll
        for (int c = 0; c < SPLITS; ++c) s += rows[r*SPLITS + c];
        float inv = 1.f / s;
        float4* pa = (float4*)(A + (long)r*NPATCH);
        #pragma unroll
        for (int q = 0; q < 4; ++q) {
            int idx = threadIdx.x + q*256;
            float4 v = pa[idx];
            v.x *= inv; v.y *= inv; v.z *= inv; v.w *= inv;
            pa[idx] = v;
        }
    }
}

// ===========================================================================
// proj_qk: Qkh[b] (fp16) = (T[b] @ Wq^T) @ Wk, one kernel.
// grid (4 n-tiles, 16 batches), 256 thr.
// Phase A: Q[32,256] = T@Wq^T in regs -> smem fp16 (Q never hits gmem).
// Phase B: Qk tile [32,128] = Q @ Wk (trans B).
// ===========================================================================
#define PJ_T     0             // 32 x 80 = 2560
#define PJ_W     2560          // max(256*80, 32*272) = 20480
#define PJ_Q     23040         // 32 x 528 = 16896
#define PJ_BYTES 39936
#define QS_PITCH 528

__global__ __launch_bounds__(256)
void proj_qk(const float* __restrict__ T, const float* __restrict__ Wq,
             const float* __restrict__ Wk, __half* __restrict__ Qkh)
{
    __shared__ __align__(16) unsigned char sm[PJ_BYTES];
    const int nb = blockIdx.x;         // 0..3
    const int b  = blockIdx.y;         // 0..15
    const int tid  = threadIdx.x;
    const int lane = tid & 31;
    const int warp = tid >> 5;
    const int mw = warp >> 2;
    const int nw = warp & 3;

    const float* Tb = T + (long)b*KTOK*DIM;

    // ---------- Phase A: Q[32,256] = Tb @ Wq^T ----------
    float accQ[8][4];
    #pragma unroll
    for (int j = 0; j < 8; ++j)
        #pragma unroll
        for (int r = 0; r < 4; ++r) accQ[j][r] = 0.f;

    const uint32_t aT = cvta_s(sm + PJ_T)
        + (mw*16 + (lane & 15))*80 + (lane >> 4)*16;
    uint32_t bW[4];
    #pragma unroll
    for (int jj = 0; jj < 4; ++jj)
        bW[jj] = cvta_s(sm + PJ_W)
            + (nw*64 + jj*16 + (lane & 7) + ((lane >> 4) & 1)*8)*80
            + ((lane >> 3) & 1)*16;

    const int am = tid >> 3, ak4 = tid & 7;

    float4 pt, pw[8];
    pt = *(const float4*)(Tb + am*DIM + 4*ak4);
    #pragma unroll
    for (int p = 0; p < 8; ++p) {
        int lin = tid + p*256;
        pw[p] = *(const float4*)(Wq + (long)(lin >> 3)*DIM + 4*(lin & 7));
    }

    for (int k0 = 0; k0 < DIM; k0 += 32) {
        *(uint2*)(sm + PJ_T + am*80 + 8*ak4) = cvt_h4(pt);
        #pragma unroll
        for (int p = 0; p < 8; ++p) {
            int lin = tid + p*256;
            *(uint2*)(sm + PJ_W + (lin >> 3)*80 + 8*(lin & 7)) = cvt_h4(pw[p]);
        }
        __syncthreads();

        int kn = k0 + 32;
        if (kn < DIM) {
            pt = *(const float4*)(Tb + am*DIM + kn + 4*ak4);
            #pragma unroll
            for (int p = 0; p < 8; ++p) {
                int lin = tid + p*256;
                pw[p] = *(const float4*)(Wq + (long)(lin >> 3)*DIM + kn + 4*(lin & 7));
            }
        }

        #pragma unroll
        for (int kt = 0; kt < 2; ++kt) {
            uint32_t a[4];
            LDSM4(a[0],a[1],a[2],a[3], aT + kt*32);
            #pragma unroll
            for (int jj = 0; jj < 4; ++jj) {
                uint32_t r0,r1,r2,r3;
                LDSM4(r0,r1,r2,r3, bW[jj] + kt*32);
                MMA_F16(accQ[2*jj],   a, r0, r1);
                MMA_F16(accQ[2*jj+1], a, r2, r3);
            }
        }
        __syncthreads();
    }

    // store Q -> smem fp16
    const int mrow = mw*16 + (lane >> 2);
    #pragma unroll
    for (int j = 0; j < 8; ++j) {
        int col = nw*64 + j*8 + 2*(lane & 3);
        __half2 h01 = __floats2half2_rn(accQ[j][0], accQ[j][1]);
        __half2 h23 = __floats2half2_rn(accQ[j][2], accQ[j][3]);
        *(uint32_t*)(sm + PJ_Q + mrow*QS_PITCH + col*2)     = *(uint32_t*)&h01;
        *(uint32_t*)(sm + PJ_Q + (mrow+8)*QS_PITCH + col*2) = *(uint32_t*)&h23;
    }
    __syncthreads();

    // ---------- Phase B: Qk[32, 128-tile] = Q(smem) @ Wk (trans) ----------
    float accK[4][4];
    #pragma unroll
    for (int j = 0; j < 4; ++j)
        #pragma unroll
        for (int r = 0; r < 4; ++r) accK[j][r] = 0.f;

    const uint32_t aQ = cvta_s(sm + PJ_Q)
        + (mw*16 + (lane & 15))*QS_PITCH + (lane >> 4)*16;
    uint32_t bK[2];
    #pragma unroll
    for (int jj = 0; jj < 2; ++jj)
        bK[jj] = cvta_s(sm + PJ_W) + (lane & 15)*272
            + (nw*32 + jj*16)*2 + ((lane >> 4) & 1)*16;

    const int n0 = nb*128;
    float4 pk[4];
    #pragma unroll
    for (int p = 0; p < 4; ++p) {
        int lin = tid + p*256;
        pk[p] = *(const float4*)(Wk + (long)(lin >> 5)*DIM + n0 + 4*(lin & 31));
    }

    for (int k0 = 0; k0 < DHEAD; k0 += 32) {
        #pragma unroll
        for (int p = 0; p < 4; ++p) {
            int lin = tid + p*256;
            *(uint2*)(sm + PJ_W + (lin >> 5)*272 + 8*(lin & 31)) = cvt_h4(pk[p]);
        }
        __syncthreads();

        int kn = k0 + 32;
        if (kn < DHEAD) {
            #pragma unroll
            for (int p = 0; p < 4; ++p) {
                int lin = tid + p*256;
                pk[p] = *(const float4*)(Wk + (long)(kn + (lin >> 5))*DIM + n0 + 4*(lin & 31));
            }
        }

        #pragma unroll
        for (int kt = 0; kt < 2; ++kt) {
            uint32_t a[4];
            LDSM4(a[0],a[1],a[2],a[3], aQ + k0*2 + kt*32);
            #pragma unroll
            for (int jj = 0; jj < 2; ++jj) {
                uint32_t r0,r1,r2,r3;
                LDSM4T(r0,r1,r2,r3, bK[jj] + kt*16*272);
                MMA_F16(accK[2*jj],   a, r0, r1);
                MMA_F16(accK[2*jj+1], a, r2, r3);
            }
        }
        __syncthreads();
    }

    // epilogue: fp16 Qk
    __half* out = Qkh + (long)b*KTOK*DIM;
    #pragma unroll
    for (int j = 0; j < 4; ++j) {
        int n = n0 + nw*32 + j*8 + 2*(lane & 3);
        __half2 h01 = __floats2half2_rn(accK[j][0], accK[j][1]);
        __half2 h23 = __floats2half2_rn(accK[j][2], accK[j][3]);
        *(uint32_t*)(out + (long)mrow*DIM + n)     = *(uint32_t*)&h01;
        *(uint32_t*)(out + (long)(mrow+8)*DIM + n) = *(uint32_t*)&h23;
    }
}

// ===========================================================================
// bf16 hi/lo split GEMM (3 MMAs, near-fp32). B = [N,Kin] row-major (NT).
// ===========================================================================
#define PITCH_A   80
#define PITCH_B   80
#define SA_H   0
#define SA_L   2560
#define SB_H   5120
#define SB_L   15360
#define SMEM_BYTES 25600

__global__ __launch_bounds__(256)
void gemm_tc_nt(const float* __restrict__ A, const float* __restrict__ B,
                float* __restrict__ C, int N, int Kin)
{
    __shared__ __align__(16) unsigned char sm[SMEM_BYTES];

    const int m0 = blockIdx.y * 32;
    const int n0 = blockIdx.x * 128;
    const int tid  = threadIdx.x;
    const int lane = tid & 31;
    const int warp = tid >> 5;
    const int mw = warp >> 2;
    const int nw = warp & 3;

    float acc[4][4];
    #pragma unroll
    for (int j = 0; j < 4; j++)
        #pragma unroll
        for (int r = 0; r < 4; r++) acc[j][r] = 0.f;

    const uint32_t aAddrH = cvta_s(sm + SA_H)
        + (mw*16 + (lane & 15))*PITCH_A + (lane >> 4)*16;
    const uint32_t aAddrL = aAddrH + (SA_L - SA_H);

    uint32_t bAddrH[2], bAddrL[2];
    #pragma unroll
    for (int jj = 0; jj < 2; jj++) {
        uint32_t nrow = nw*32 + jj*16 + (lane & 7) + ((lane >> 4) & 1)*8;
        bAddrH[jj] = cvta_s(sm + SB_H) + nrow*PITCH_B + ((lane >> 3) & 1)*16;
        bAddrL[jj] = bAddrH[jj] + (SB_L - SB_H);
    }

    for (int k0 = 0; k0 < Kin; k0 += 32) {
        {
            int m  = tid >> 3, k4 = tid & 7;
            float4 v = *(const float4*)(A + (long)(m0+m)*Kin + k0 + 4*k4);
            uint2 hi, lo; cvt_split4(v, hi, lo);
            *(uint2*)(sm + SA_H + m*PITCH_A + 8*k4) = hi;
            *(uint2*)(sm + SA_L + m*PITCH_A + 8*k4) = lo;
        }
        #pragma unroll
        for (int p = 0; p < 4; ++p) {
            int lin = tid + p*256;
            int n = lin >> 3, k4 = lin & 7;
            float4 v = *(const float4*)(B + (long)(n0+n)*Kin + k0 + 4*k4);
            uint2 hi, lo; cvt_split4(v, hi, lo);
            *(uint2*)(sm + SB_H + n*PITCH_B + 8*k4) = hi;
            *(uint2*)(sm + SB_L + n*PITCH_B + 8*k4) = lo;
        }
        __syncthreads();

        #pragma unroll
        for (int kt = 0; kt < 2; ++kt) {
            uint32_t ah[4], al[4];
            LDSM4(ah[0],ah[1],ah[2],ah[3], aAddrH + kt*32);
            LDSM4(al[0],al[1],al[2],al[3], aAddrL + kt*32);
            uint32_t bh[4][2], bl[4][2];
            #pragma unroll
            for (int jj = 0; jj < 2; ++jj) {
                uint32_t r0,r1,r2,r3;
                LDSM4(r0,r1,r2,r3, bAddrH[jj] + kt*32);
                bh[2*jj][0]=r0; bh[2*jj][1]=r1; bh[2*jj+1][0]=r2; bh[2*jj+1][1]=r3;
                LDSM4(r0,r1,r2,r3, bAddrL[jj] + kt*32);
                bl[2*jj][0]=r0; bl[2*jj][1]=r1; bl[2*jj+1][0]=r2; bl[2*jj+1][1]=r3;
            }
            #pragma unroll
            for (int j = 0; j < 4; ++j) {
                MMA_BF16(acc[j], ah, bh[j][0], bh[j][1]);
                MMA_BF16(acc[j], ah, bl[j][0], bl[j][1]);
                MMA_BF16(acc[j], al, bh[j][0], bh[j][1]);
            }
        }
        __syncthreads();
    }

    const int mrow = m0 + mw*16 + (lane >> 2);
    #pragma unroll
    for (int j = 0; j < 4; ++j) {
        int n = n0 + nw*32 + j*8 + 2*(lane & 3);
        C[(long)mrow*N + n]       = acc[j][0];
        C[(long)mrow*N + n + 1]   = acc[j][1];
        C[(long)(mrow+8)*N + n]   = acc[j][2];
        C[(long)(mrow+8)*N + n+1] = acc[j][3];
    }
}

// ---------------------------------------------------------------------------
__global__ void normalize_rows(float* __restrict__ C)
{
    const int row = blockIdx.x;
    float* p = C + (long)row * DIM;
    const int t = threadIdx.x;
    float v[4]; float ss = 0.f;
    #pragma unroll
    for (int i = 0; i < 4; i++) { v[i] = p[t + i*128]; ss += v[i]*v[i]; }
    __shared__ float red[128];
    red[t] = ss; __syncthreads();
    #pragma unroll
    for (int s = 64; s > 0; s >>= 1) {
        if (t < s) red[t] += red[t+s];
        __syncthreads();
    }
    float inv = 1.f / (sqrtf(red[0]) + 1e-8f);
    #pragma unroll
    for (int i = 0; i < 4; i++) p[t + i*128] = v[i] * inv;
}

extern "C" void kernel_launch(void* const* d_in, const int* in_sizes, int n_in,
                              void* d_out, int out_size)
{
    const float* E  = (const float*)d_in[0];
    const float* T  = (const float*)d_in[1];
    const float* P  = (const float*)d_in[2];
    const float* Wq = (const float*)d_in[3];
    const float* Wk = (const float*)d_in[4];
    const float* Wv = (const float*)d_in[5];
    const float* Wo = (const float*)d_in[6];

    float* outF = (float*)d_out;
    float* outA = (float*)d_out + (long)BATCH*KTOK*DIM;

    float *pGp, *pG, *pF, *pRows;
    __half* pQkh;
    cudaGetSymbolAddress((void**)&pQkh,  g_Qkh);
    cudaGetSymbolAddress((void**)&pGp,   g_Gp);
    cudaGetSymbolAddress((void**)&pG,    g_G);
    cudaGetSymbolAddress((void**)&pF,    g_F);
    cudaGetSymbolAddress((void**)&pRows, g_rows);

    cudaFuncSetAttribute(fused_attn4,
        cudaFuncAttributeMaxDynamicSharedMemorySize, SMEM_FUSED);

    dim3 blk(256);

    // 1) Qk = (T @ Wq^T) @ Wk  (merged, fp16 out)
    proj_qk<<<dim3(4, BATCH), blk>>>(T, Wq, Wk, pQkh);

    // 2) FUSED: expS/A(unnorm) + row-sum partials + G partials
    fused_attn4<<<dim3(SPLITS, BATCH), blk, SMEM_FUSED>>>(
        pQkh, E, P, outA, pGp, pRows);

    // 3) post: G reduce (256 blocks) + A row-scale (512 blocks)
    post_kernel<<<768, blk>>>(pGp, pG, pRows, outA);

    // 4) F = G @ Wv^T  (bf16 hi/lo)
    gemm_tc_nt<<<dim3(DHEAD/128, 16), blk>>>(pG, Wv, pF, DHEAD, DIM);

    // 5) out = F @ Wo^T  (bf16 hi/lo)
    gemm_tc_nt<<<dim3(DIM/128, 16), blk>>>(pF, Wo, outF, DIM, DHEAD);

    // 6) L2-normalize outF rows
    normalize_rows<<<BATCH*KTOK, 128>>>(outF);
}